// round 5
// baseline (speedup 1.0000x reference)
#include <cuda_runtime.h>

// Problem constants (fixed by setup_inputs)
#define NB        64
#define SD        52
#define CELLS     (SD * SD)             // 2704
#define CH        255
#define QCELLS    4                     // cells per quad
#define QF        (QCELLS * CH)         // 1020 floats per tensor per quad
#define QF4       (QF / 4)              // 255 float4
#define QBYTES    (2 * QF * 4)          // 8160 B per quad (H+Y)
#define NQUADS    (NB * CELLS / QCELLS) // 43264
#define WPB       4                     // warps per block
#define THREADS   (WPB * 32)
#define GRIDB     444                   // 3 blocks/SM * 148
#define NWARPS    (GRIDB * WPB)         // 1776
#define SMEM_BYTES (WPB * 2 * QBYTES)   // 65280
#define EPSF      1e-6f
#define IOU_T     0.7f
#define SCALE_IDX 2

__global__ void zero_out_kernel(float* out) {
    int t = threadIdx.x;
    if (t < 257) out[t] = 0.0f;
}

__device__ __forceinline__ float warp_sum(float v) {
    #pragma unroll
    for (int o = 16; o > 0; o >>= 1) v += __shfl_down_sync(0xffffffffu, v, o);
    return v;
}

// Issue cp.async for one quad (both tensors) into a warp-private buffer.
// 16 predicated 16B copies per lane; no registers held.
__device__ __forceinline__ void prefetch_quad(const float* __restrict__ yhat,
                                              const float* __restrict__ ytru,
                                              int q, unsigned sbuf, int lane) {
    const float* gH = yhat + (size_t)q * QF;
    const float* gY = ytru + (size_t)q * QF;
    unsigned dH = sbuf;
    unsigned dY = sbuf + QF * 4;
    #pragma unroll
    for (int k = 0; k < 8; k++) {
        int i = k * 32 + lane;                 // 0..255 (255 valid)
        if (i < QF4) {
            asm volatile("cp.async.cg.shared.global [%0], [%1], 16;\n"
                         :: "r"(dH + i * 16), "l"(gH + i * 4));
            asm volatile("cp.async.cg.shared.global [%0], [%1], 16;\n"
                         :: "r"(dY + i * 16), "l"(gY + i * 4));
        }
    }
}

__device__ __forceinline__ void compute_quad(const float* __restrict__ sH,
                                             const float* __restrict__ sY,
                                             const float* __restrict__ anchors,
                                             float* __restrict__ out,
                                             int q, int lane) {
    const int n  = q / (CELLS / QCELLS);
    const int c0 = (q % (CELLS / QCELLS)) * QCELLS;
    const int g   = lane >> 3;        // cell within quad
    const int sub = lane & 7;
    const int cellIdx = c0 + g;
    const int gi = cellIdx / SD;
    const int gj = cellIdx % SD;

    const float* H = sH + g * CH;
    const float* Y = sY + g * CH;

    float hx[3], hy[3], hw[3], hh[3], hc[3];
    float yx[3], yy[3], yw[3], yh[3], yc[3];
    #pragma unroll
    for (int b = 0; b < 3; b++) {
        const float* hb = H + b * 85;
        const float* yb = Y + b * 85;
        hx[b] = hb[0]; hy[b] = hb[1]; hw[b] = hb[2]; hh[b] = hb[3]; hc[b] = hb[4];
        yx[b] = yb[0]; yy[b] = yb[1]; yw[b] = yb[2]; yh[b] = yb[3]; yc[b] = yb[4];
    }

    const float invS = 1.0f / (float)SD;
    const float fj = (float)gj, fi = (float)gi;

    float hx1[3], hx2[3], hy1[3], hy2[3];
    float tx1[3], tx2[3], ty1[3], ty2[3];
    #pragma unroll
    for (int b = 0; b < 3; b++) {
        float cx = (hx[b] + fj) * invS, cy = (hy[b] + fi) * invS;
        hx1[b] = cx - 0.5f * hw[b]; hx2[b] = cx + 0.5f * hw[b];
        hy1[b] = cy - 0.5f * hh[b]; hy2[b] = cy + 0.5f * hh[b];
        cx = (yx[b] + fj) * invS; cy = (yy[b] + fi) * invS;
        tx1[b] = cx - 0.5f * yw[b]; tx2[b] = cx + 0.5f * yw[b];
        ty1[b] = cy - 0.5f * yh[b]; ty2[b] = cy + 0.5f * yh[b];
    }

    // IOU 3x3: per-pb max (noobj mask), per-tb argmax (responsible predictor).
    int   idx_t[3];
    float best_t[3] = {-1.0f, -1.0f, -1.0f};
    float noobj_f[3];
    #pragma unroll
    for (int pb = 0; pb < 3; pb++) {
        float pa = hw[pb] * hh[pb];
        float m = -1.0f;
        #pragma unroll
        for (int tb = 0; tb < 3; tb++) {
            float wi = fmaxf(fminf(hx2[pb], tx2[tb]) - fmaxf(hx1[pb], tx1[tb]), 0.0f);
            float hi = fmaxf(fminf(hy2[pb], ty2[tb]) - fmaxf(hy1[pb], ty1[tb]), 0.0f);
            float inter = wi * hi;
            float uni = pa + yw[tb] * yh[tb] - inter;
            float iou = inter / (uni + EPSF);
            m = fmaxf(m, iou);
            if (iou > best_t[tb]) { best_t[tb] = iou; idx_t[tb] = pb; }
        }
        noobj_f[pb] = (m < IOU_T) ? 1.0f : 0.0f;
    }

    float coord_acc = 0.0f, cls_acc = 0.0f, noobj_acc = 0.0f, obj_acc = 0.0f;

    if (sub == 0) {
        const float* anc = anchors + SCALE_IDX * 6;
        #pragma unroll
        for (int tb = 0; tb < 3; tb++) {
            int pb = idx_t[tb];
            float ho = (yc[tb] > 0.0f) ? 1.0f : 0.0f;
            float aw_p = __ldg(anc + pb * 2), ah_p = __ldg(anc + pb * 2 + 1);
            float aw_t = __ldg(anc + tb * 2), ah_t = __ldg(anc + tb * 2 + 1);
            float dx = hx[pb] - yx[tb];
            float dy = hy[pb] - yy[tb];
            float dlw = __logf(hw[pb] / aw_p + EPSF) - __logf(yw[tb] / aw_t + EPSF);
            float dlh = __logf(hh[pb] / ah_p + EPSF) - __logf(yh[tb] / ah_t + EPSF);
            float c = dx * dx + dy * dy + dlw * dlw + dlh * dlh;
            coord_acc += c * ho * (2.0f - yw[tb] * yh[tb]);   // SCALE_COORD
            float dc = hc[pb] - yc[tb];
            obj_acc += dc * dc * ho;
            noobj_acc += hc[tb] * hc[tb] * noobj_f[tb];        // NO_OBJ_V3
        }
    }

    // Class loss: 3 tb x 80 classes split across the 8 lanes of this cell.
    #pragma unroll
    for (int tb = 0; tb < 3; tb++) {
        int pb = idx_t[tb];
        float ho = (yc[tb] > 0.0f) ? 1.0f : 0.0f;
        const float* Hc = H + pb * 85 + 5;
        const float* Yc = Y + tb * 85 + 5;
        float s = 0.0f;
        #pragma unroll
        for (int c = sub; c < 80; c += 8) {
            float d = Hc[c] - Yc[c];
            s += d * d;
        }
        cls_acc += s * ho;
    }

    coord_acc = warp_sum(coord_acc);
    cls_acc   = warp_sum(cls_acc);
    noobj_acc = warp_sum(noobj_acc);
    obj_acc   = warp_sum(obj_acc);

    if (lane == 0) {
        // layout: coord[0:64) class[64:128) noobj[128:192) obj[192:256) prior[256]
        atomicAdd(out + 0 * NB + n, coord_acc);
        atomicAdd(out + 1 * NB + n, cls_acc);
        atomicAdd(out + 2 * NB + n, noobj_acc);
        atomicAdd(out + 3 * NB + n, obj_acc);
    }
}

__global__ __launch_bounds__(THREADS) void yolo_loss_kernel(
    const float* __restrict__ yhat,
    const float* __restrict__ ytru,
    const float* __restrict__ anchors,
    float* __restrict__ out)
{
    extern __shared__ float smem[];   // [WPB][2 bufs][H|Y]

    const int wl   = threadIdx.x >> 5;
    const int lane = threadIdx.x & 31;
    const int w0   = blockIdx.x * WPB + wl;    // global warp id, 0..1775

    float* buf0 = smem + wl * 2 * (2 * QF);
    float* buf1 = buf0 + 2 * QF;
    unsigned sb0 = (unsigned)__cvta_generic_to_shared(buf0);
    unsigned sb1 = (unsigned)__cvta_generic_to_shared(buf1);

    // Prologue: prefetch first quad.
    if (w0 < NQUADS) prefetch_quad(yhat, ytru, w0, sb0, lane);
    asm volatile("cp.async.commit_group;\n" ::: "memory");

    int cur = 0;
    for (int q = w0; q < NQUADS; q += NWARPS) {
        int qn = q + NWARPS;
        if (qn < NQUADS)
            prefetch_quad(yhat, ytru, qn, cur ? sb0 : sb1, lane);
        asm volatile("cp.async.commit_group;\n" ::: "memory");
        asm volatile("cp.async.wait_group 1;\n" ::: "memory");
        __syncwarp();

        const float* b = cur ? buf1 : buf0;
        compute_quad(b, b + QF, anchors, out, q, lane);

        __syncwarp();   // all lanes done reading before this buffer is refilled
        cur ^= 1;
    }
}

extern "C" void kernel_launch(void* const* d_in, const int* in_sizes, int n_in,
                              void* d_out, int out_size) {
    const float* yhat    = (const float*)d_in[0];
    const float* y       = (const float*)d_in[1];
    const float* anchors = (const float*)d_in[2];
    float* out = (float*)d_out;

    cudaFuncSetAttribute(yolo_loss_kernel,
                         cudaFuncAttributeMaxDynamicSharedMemorySize, SMEM_BYTES);

    zero_out_kernel<<<1, 288>>>(out);
    yolo_loss_kernel<<<GRIDB, THREADS, SMEM_BYTES>>>(yhat, y, anchors, out);
}

// round 6
// speedup vs baseline: 1.1587x; 1.1587x over previous
#include <cuda_runtime.h>

// Problem constants (fixed by setup_inputs)
#define NB        64
#define SD        52
#define CELLS     (SD * SD)             // 2704
#define CH        255
#define QCELLS    4                     // cells per warp
#define NQUADS    (NB * CELLS / QCELLS) // 43264
#define CPI       (CELLS / QCELLS)      // 676 quads per image
#define EPSF      1e-6f
#define IOU_T     0.7f
#define SCALE_IDX 2

__global__ void zero_out_kernel(float* out) {
    int t = threadIdx.x;
    if (t < 257) out[t] = 0.0f;
}

__device__ __forceinline__ float warp_sum(float v) {
    #pragma unroll
    for (int o = 16; o > 0; o >>= 1) v += __shfl_down_sync(0xffffffffu, v, o);
    return v;
}

__global__ __launch_bounds__(128, 8) void yolo_loss_kernel(
    const float* __restrict__ yhat,
    const float* __restrict__ ytru,
    const float* __restrict__ anchors,
    float* __restrict__ out)
{
    const int wl   = threadIdx.x >> 5;
    const int lane = threadIdx.x & 31;
    const int quad = blockIdx.x * 4 + wl;     // 0..43263 (grid exact)
    const int n    = quad / CPI;              // image
    const int c0   = (quad % CPI) * QCELLS;

    const int g   = lane >> 3;                // cell within quad (0..3)
    const int sub = lane & 7;                 // lane within cell group
    const int cellIdx = c0 + g;
    const int gi = cellIdx / SD;
    const int gj = cellIdx % SD;

    const size_t base = ((size_t)n * CELLS + cellIdx) * CH;
    const float* Hb = yhat + base;
    const float* Yb = ytru + base;

    // ---- Box fields: 30 independent broadcast LDGs per warp (4 sectors each).
    // Keep absolute-center form to minimize live registers.
    const float invS = 1.0f / (float)SD;
    const float fj = (float)gj, fi = (float)gi;

    float hcx[3], hcy[3], hw[3], hh[3], hcf[3];
    float ycx[3], ycy[3], yw[3], yh[3], ycf[3];
    #pragma unroll
    for (int b = 0; b < 3; b++) {
        const float* hb = Hb + b * 85;
        const float* yb = Yb + b * 85;
        hcx[b] = (__ldg(hb + 0) + fj) * invS;
        hcy[b] = (__ldg(hb + 1) + fi) * invS;
        hw[b]  =  __ldg(hb + 2);
        hh[b]  =  __ldg(hb + 3);
        hcf[b] =  __ldg(hb + 4);
        ycx[b] = (__ldg(yb + 0) + fj) * invS;
        ycy[b] = (__ldg(yb + 1) + fi) * invS;
        yw[b]  =  __ldg(yb + 2);
        yh[b]  =  __ldg(yb + 3);
        ycf[b] =  __ldg(yb + 4);
    }

    // ---- IOU 3x3: per-pb max -> noobj term; per-tb argmax -> responsible box.
    int   idx_t[3];
    float best_t[3] = {-1.0f, -1.0f, -1.0f};
    float noobj_acc = 0.0f;
    #pragma unroll
    for (int pb = 0; pb < 3; pb++) {
        float px1 = hcx[pb] - 0.5f * hw[pb], px2 = hcx[pb] + 0.5f * hw[pb];
        float py1 = hcy[pb] - 0.5f * hh[pb], py2 = hcy[pb] + 0.5f * hh[pb];
        float pa  = hw[pb] * hh[pb];
        float m = -1.0f;
        #pragma unroll
        for (int tb = 0; tb < 3; tb++) {
            float wi = fmaxf(fminf(px2, ycx[tb] + 0.5f * yw[tb]) -
                             fmaxf(px1, ycx[tb] - 0.5f * yw[tb]), 0.0f);
            float hi = fmaxf(fminf(py2, ycy[tb] + 0.5f * yh[tb]) -
                             fmaxf(py1, ycy[tb] - 0.5f * yh[tb]), 0.0f);
            float inter = wi * hi;
            float uni = pa + yw[tb] * yh[tb] - inter;
            float iou = inter / (uni + EPSF);
            m = fmaxf(m, iou);
            if (iou > best_t[tb]) { best_t[tb] = iou; idx_t[tb] = pb; }
        }
        if (sub == 0 && m < IOU_T) noobj_acc += hcf[pb] * hcf[pb];  // NO_OBJ_V3
    }

    // ---- Scalar losses (one lane per cell).
    float coord_acc = 0.0f, obj_acc = 0.0f;
    if (sub == 0) {
        const float* anc = anchors + SCALE_IDX * 6;
        #pragma unroll
        for (int tb = 0; tb < 3; tb++) {
            int pb = idx_t[tb];
            float ho = (ycf[tb] > 0.0f) ? 1.0f : 0.0f;
            float aw_p = __ldg(anc + pb * 2), ah_p = __ldg(anc + pb * 2 + 1);
            float aw_t = __ldg(anc + tb * 2), ah_t = __ldg(anc + tb * 2 + 1);
            float dx = (hcx[pb] - ycx[tb]) * (float)SD;   // == x_hat - x_true
            float dy = (hcy[pb] - ycy[tb]) * (float)SD;
            float dlw = __logf(hw[pb] / aw_p + EPSF) - __logf(yw[tb] / aw_t + EPSF);
            float dlh = __logf(hh[pb] / ah_p + EPSF) - __logf(yh[tb] / ah_t + EPSF);
            float c = dx * dx + dy * dy + dlw * dlw + dlh * dlh;
            coord_acc += c * ho * (2.0f - yw[tb] * yh[tb]);   // SCALE_COORD
            float dc = hcf[pb] - ycf[tb];
            obj_acc += dc * dc * ho;
        }
    }

    // ---- Class loss: stream straight from global, coalesced 32B sectors.
    // Only the argmax-selected yhat boxes' class channels are ever loaded.
    float cls_acc = 0.0f;
    #pragma unroll
    for (int tb = 0; tb < 3; tb++) {
        int pb = idx_t[tb];
        float ho = (ycf[tb] > 0.0f) ? 1.0f : 0.0f;
        const float* Hc = Hb + pb * 85 + 5;
        const float* Yc = Yb + tb * 85 + 5;
        float s = 0.0f;
        #pragma unroll
        for (int c = sub; c < 80; c += 8) {
            float d = __ldg(Hc + c) - __ldg(Yc + c);
            s += d * d;
        }
        cls_acc += s * ho;
    }

    // ---- Warp reduction (all 4 cells share image n) + atomics.
    coord_acc = warp_sum(coord_acc);
    cls_acc   = warp_sum(cls_acc);
    noobj_acc = warp_sum(noobj_acc);
    obj_acc   = warp_sum(obj_acc);

    if (lane == 0) {
        // layout: coord[0:64) class[64:128) noobj[128:192) obj[192:256) prior[256]
        atomicAdd(out + 0 * NB + n, coord_acc);
        atomicAdd(out + 1 * NB + n, cls_acc);
        atomicAdd(out + 2 * NB + n, noobj_acc);
        atomicAdd(out + 3 * NB + n, obj_acc);
    }
}

extern "C" void kernel_launch(void* const* d_in, const int* in_sizes, int n_in,
                              void* d_out, int out_size) {
    const float* yhat    = (const float*)d_in[0];
    const float* y       = (const float*)d_in[1];
    const float* anchors = (const float*)d_in[2];
    float* out = (float*)d_out;

    zero_out_kernel<<<1, 288>>>(out);
    yolo_loss_kernel<<<NQUADS / 4, 128>>>(yhat, y, anchors, out);  // 10816 blocks
}